// round 3
// baseline (speedup 1.0000x reference)
#include <cuda_runtime.h>
#include <cuda_bf16.h>
#include <math.h>

// FactorizedPrior: z_hat = round(z); likelihoods = clip(cdf(z_hat+0.5)-cdf(z_hat-0.5), 1e-9)
// cdf = sigmoid( 4-layer per-channel tiny MLP with softplus'd weights ).
// With factors f==0 (the dataset), the whole MLP is affine per channel:
//   logit(x) = a[c]*x + d[c]
// Precomposed once in a 192-thread setup kernel; main kernel is memory-bound:
// 1 rint + ~4 FMA + 3 MUFU per element.

#define NCH 192
#define NB 32
#define NHW 4096                 // 64*64
#define NELEM (NB * NCH * NHW)   // 25165824
#define N4 (NELEM / 4)           // 6291456 float4s
#define HW4 1024                 // float4 per (b,c) plane
#define GRID_MAIN 2368           // 148 SMs * 16 blocks

struct ChParams {
    float w0[3], W1[9], W2[9], w3[3];
    float b0[3], b1[3], b2[3], b3;
    float tf0[3], tf1[3], tf2[3];
};

__device__ ChParams g_ch[NCH];
__device__ float4   g_ad[NCH];   // {a, d, exp(a), 0.5a}
__device__ int      g_flag;      // nonzero if any factor f != 0 -> general path

__device__ __forceinline__ float softplus_f(float x) {
    // stable log(1+e^x)
    return (x > 0.f) ? x + log1pf(expf(-x)) : log1pf(expf(x));
}

__global__ void setup_kernel(const float* __restrict__ m0, const float* __restrict__ m1,
                             const float* __restrict__ m2, const float* __restrict__ m3,
                             const float* __restrict__ b0, const float* __restrict__ b1,
                             const float* __restrict__ b2, const float* __restrict__ b3,
                             const float* __restrict__ f0, const float* __restrict__ f1,
                             const float* __restrict__ f2) {
    __shared__ int s_nz[256];
    int c = threadIdx.x;
    int nz = 0;

    if (c < NCH) {
        ChParams& P = g_ch[c];
        #pragma unroll
        for (int i = 0; i < 3; i++) P.w0[i] = softplus_f(m0[c * 3 + i]);
        #pragma unroll
        for (int i = 0; i < 9; i++) P.W1[i] = softplus_f(m1[c * 9 + i]);
        #pragma unroll
        for (int i = 0; i < 9; i++) P.W2[i] = softplus_f(m2[c * 9 + i]);
        #pragma unroll
        for (int i = 0; i < 3; i++) P.w3[i] = softplus_f(m3[c * 3 + i]);
        #pragma unroll
        for (int i = 0; i < 3; i++) P.b0[i] = b0[c * 3 + i];
        #pragma unroll
        for (int i = 0; i < 3; i++) P.b1[i] = b1[c * 3 + i];
        #pragma unroll
        for (int i = 0; i < 3; i++) P.b2[i] = b2[c * 3 + i];
        P.b3 = b3[c];

        #pragma unroll
        for (int i = 0; i < 3; i++) { P.tf0[i] = tanhf(f0[c * 3 + i]); nz |= (P.tf0[i] != 0.f); }
        #pragma unroll
        for (int i = 0; i < 3; i++) { P.tf1[i] = tanhf(f1[c * 3 + i]); nz |= (P.tf1[i] != 0.f); }
        #pragma unroll
        for (int i = 0; i < 3; i++) { P.tf2[i] = tanhf(f2[c * 3 + i]); nz |= (P.tf2[i] != 0.f); }

        // Affine precomposition (exact when all tf == 0)
        float va[3], vd[3];
        #pragma unroll
        for (int i = 0; i < 3; i++) { va[i] = P.w0[i]; vd[i] = P.b0[i]; }

        float ta[3], td[3];
        #pragma unroll
        for (int r = 0; r < 3; r++) {
            ta[r] = P.W1[r * 3 + 0] * va[0] + P.W1[r * 3 + 1] * va[1] + P.W1[r * 3 + 2] * va[2];
            td[r] = P.W1[r * 3 + 0] * vd[0] + P.W1[r * 3 + 1] * vd[1] + P.W1[r * 3 + 2] * vd[2] + P.b1[r];
        }
        #pragma unroll
        for (int r = 0; r < 3; r++) {
            va[r] = P.W2[r * 3 + 0] * ta[0] + P.W2[r * 3 + 1] * ta[1] + P.W2[r * 3 + 2] * ta[2];
            vd[r] = P.W2[r * 3 + 0] * td[0] + P.W2[r * 3 + 1] * td[1] + P.W2[r * 3 + 2] * td[2] + P.b2[r];
        }
        float a = P.w3[0] * va[0] + P.w3[1] * va[1] + P.w3[2] * va[2];
        float d = P.w3[0] * vd[0] + P.w3[1] * vd[1] + P.w3[2] * vd[2] + P.b3;

        g_ad[c] = make_float4(a, d, expf(a), 0.5f * a);
    }

    s_nz[threadIdx.x] = nz;
    __syncthreads();
    if (threadIdx.x == 0) {
        int any = 0;
        for (int i = 0; i < NCH; i++) any |= s_nz[i];
        g_flag = any;
    }
}

// Full per-element MLP (only used if any factor is nonzero).
__device__ __noinline__ float cdf_general(const ChParams& P, float x) {
    float v[3], u[3];
    #pragma unroll
    for (int r = 0; r < 3; r++) {
        v[r] = fmaf(P.w0[r], x, P.b0[r]);
        v[r] = fmaf(P.tf0[r], tanhf(v[r]), v[r]);
    }
    #pragma unroll
    for (int r = 0; r < 3; r++) {
        u[r] = P.W1[r * 3 + 0] * v[0] + P.W1[r * 3 + 1] * v[1] + P.W1[r * 3 + 2] * v[2] + P.b1[r];
        u[r] = fmaf(P.tf1[r], tanhf(u[r]), u[r]);
    }
    #pragma unroll
    for (int r = 0; r < 3; r++) {
        v[r] = P.W2[r * 3 + 0] * u[0] + P.W2[r * 3 + 1] * u[1] + P.W2[r * 3 + 2] * u[2] + P.b2[r];
        v[r] = fmaf(P.tf2[r], tanhf(v[r]), v[r]);
    }
    float l = P.w3[0] * v[0] + P.w3[1] * v[1] + P.w3[2] * v[2] + P.b3;
    return __fdividef(1.f, 1.f + __expf(-l));
}

__global__ void __launch_bounds__(256) fp_main_kernel(const float4* __restrict__ z,
                                                      float* __restrict__ out) {
    int flag = g_flag;
    for (int i = blockIdx.x * 256 + threadIdx.x; i < N4; i += GRID_MAIN * 256) {
        int c = (i >> 10) % NCH;   // HW4 = 1024 float4 per plane

        float4 zv = z[i];
        float4 zh, lk;

        if (flag == 0) {
            float4 p = g_ad[c];    // {a, d, K=e^a, h=0.5a}
            #pragma unroll
            for (int j = 0; j < 4; j++) {
                float x  = rintf((&zv.x)[j]);                  // round half-to-even == jnp.round
                float t  = fmaf(p.x, x, p.y);
                float E  = __expf(-(t + p.w));                 // e^{-(t+h)}
                float up = __fdividef(1.f, 1.f + E);           // sigmoid(t+h)
                float lo = __fdividef(1.f, fmaf(E, p.z, 1.f)); // sigmoid(t-h): e^{-(t-h)} = E*e^{a}
                (&zh.x)[j] = x;
                (&lk.x)[j] = fmaxf(up - lo, 1e-9f);
            }
        } else {
            const ChParams& P = g_ch[c];
            #pragma unroll
            for (int j = 0; j < 4; j++) {
                float x  = rintf((&zv.x)[j]);
                float up = cdf_general(P, x + 0.5f);
                float lo = cdf_general(P, x - 0.5f);
                (&zh.x)[j] = x;
                (&lk.x)[j] = fmaxf(up - lo, 1e-9f);
            }
        }

        reinterpret_cast<float4*>(out)[i] = zh;               // z_hat  [0, N)
        reinterpret_cast<float4*>(out + NELEM)[i] = lk;       // likes  [N, 2N)
    }
}

extern "C" void kernel_launch(void* const* d_in, const int* in_sizes, int n_in,
                              void* d_out, int out_size) {
    const float* z  = (const float*)d_in[0];
    const float* m0 = (const float*)d_in[1];
    const float* m1 = (const float*)d_in[2];
    const float* m2 = (const float*)d_in[3];
    const float* m3 = (const float*)d_in[4];
    const float* b0 = (const float*)d_in[5];
    const float* b1 = (const float*)d_in[6];
    const float* b2 = (const float*)d_in[7];
    const float* b3 = (const float*)d_in[8];
    const float* f0 = (const float*)d_in[9];
    const float* f1 = (const float*)d_in[10];
    const float* f2 = (const float*)d_in[11];

    setup_kernel<<<1, 256>>>(m0, m1, m2, m3, b0, b1, b2, b3, f0, f1, f2);
    fp_main_kernel<<<GRID_MAIN, 256>>>((const float4*)z, (float*)d_out);
}

// round 5
// speedup vs baseline: 1.0717x; 1.0717x over previous
#include <cuda_runtime.h>
#include <cuda_bf16.h>
#include <math.h>

// FactorizedPrior: z_hat = round(z); likelihoods = clip(cdf(z_hat+0.5)-cdf(z_hat-0.5), 1e-9)
// cdf = sigmoid( 4-layer per-channel tiny MLP with softplus'd weights ).
// With factors f==0 (the dataset), the MLP collapses to logit = a[c]*x + d[c],
// precomposed once in a tiny setup kernel (fast-math; accuracy budget is huge
// vs the 1e-3 threshold). Main kernel: streaming, ILP=2, evict-first ld/st.

#define NCH 192
#define NB 32
#define NHW 4096                 // 64*64
#define NELEM (NB * NCH * NHW)   // 25165824
#define N4 (NELEM / 4)           // 6291456 float4s
#define GRID_MAIN 2368           // 148 SMs * 16 blocks
#define CHUNK (GRID_MAIN * 512)  // float4s consumed per grid sweep (ILP=2)

struct ChParams {
    float w0[3], W1[9], W2[9], w3[3];
    float b0[3], b1[3], b2[3], b3;
    float tf0[3], tf1[3], tf2[3];
};

__device__ ChParams g_ch[NCH];
__device__ float4   g_ad[NCH];   // {a, d, exp(a), 0.5a}
__device__ int      g_flag;      // nonzero if any factor f != 0 -> general path

__device__ __forceinline__ float softplus_fast(float x) {
    // log(1+e^x) = max(x,0) + log(1+e^-|x|), fast-math MUFU version.
    float e = __expf(-fabsf(x));
    return fmaxf(x, 0.f) + __logf(1.f + e);
}

__device__ __forceinline__ float tanh_fast(float x) {
    float y;
    asm("tanh.approx.f32 %0, %1;" : "=f"(y) : "f"(x));
    return y;  // exact 0 at x==0
}

__global__ void setup_kernel(const float* __restrict__ m0, const float* __restrict__ m1,
                             const float* __restrict__ m2, const float* __restrict__ m3,
                             const float* __restrict__ b0, const float* __restrict__ b1,
                             const float* __restrict__ b2, const float* __restrict__ b3,
                             const float* __restrict__ f0, const float* __restrict__ f1,
                             const float* __restrict__ f2) {
    int c = threadIdx.x;
    int nz = 0;

    if (c < NCH) {
        ChParams& P = g_ch[c];
        #pragma unroll
        for (int i = 0; i < 3; i++) P.w0[i] = softplus_fast(m0[c * 3 + i]);
        #pragma unroll
        for (int i = 0; i < 9; i++) P.W1[i] = softplus_fast(m1[c * 9 + i]);
        #pragma unroll
        for (int i = 0; i < 9; i++) P.W2[i] = softplus_fast(m2[c * 9 + i]);
        #pragma unroll
        for (int i = 0; i < 3; i++) P.w3[i] = softplus_fast(m3[c * 3 + i]);
        #pragma unroll
        for (int i = 0; i < 3; i++) P.b0[i] = b0[c * 3 + i];
        #pragma unroll
        for (int i = 0; i < 3; i++) P.b1[i] = b1[c * 3 + i];
        #pragma unroll
        for (int i = 0; i < 3; i++) P.b2[i] = b2[c * 3 + i];
        P.b3 = b3[c];

        #pragma unroll
        for (int i = 0; i < 3; i++) { P.tf0[i] = tanh_fast(f0[c * 3 + i]); nz |= (P.tf0[i] != 0.f); }
        #pragma unroll
        for (int i = 0; i < 3; i++) { P.tf1[i] = tanh_fast(f1[c * 3 + i]); nz |= (P.tf1[i] != 0.f); }
        #pragma unroll
        for (int i = 0; i < 3; i++) { P.tf2[i] = tanh_fast(f2[c * 3 + i]); nz |= (P.tf2[i] != 0.f); }

        // Affine precomposition (exact when all tf == 0)
        float va[3], vd[3];
        #pragma unroll
        for (int i = 0; i < 3; i++) { va[i] = P.w0[i]; vd[i] = P.b0[i]; }

        float ta[3], td[3];
        #pragma unroll
        for (int r = 0; r < 3; r++) {
            ta[r] = P.W1[r * 3 + 0] * va[0] + P.W1[r * 3 + 1] * va[1] + P.W1[r * 3 + 2] * va[2];
            td[r] = P.W1[r * 3 + 0] * vd[0] + P.W1[r * 3 + 1] * vd[1] + P.W1[r * 3 + 2] * vd[2] + P.b1[r];
        }
        #pragma unroll
        for (int r = 0; r < 3; r++) {
            va[r] = P.W2[r * 3 + 0] * ta[0] + P.W2[r * 3 + 1] * ta[1] + P.W2[r * 3 + 2] * ta[2];
            vd[r] = P.W2[r * 3 + 0] * td[0] + P.W2[r * 3 + 1] * td[1] + P.W2[r * 3 + 2] * td[2] + P.b2[r];
        }
        float a = P.w3[0] * va[0] + P.w3[1] * va[1] + P.w3[2] * va[2];
        float d = P.w3[0] * vd[0] + P.w3[1] * vd[1] + P.w3[2] * vd[2] + P.b3;

        g_ad[c] = make_float4(a, d, __expf(a), 0.5f * a);
    }

    int any = __syncthreads_or(nz);
    if (threadIdx.x == 0) g_flag = any;
}

// Full per-element MLP (only used if any factor is nonzero).
__device__ __noinline__ float cdf_general(const ChParams& P, float x) {
    float v[3], u[3];
    #pragma unroll
    for (int r = 0; r < 3; r++) {
        v[r] = fmaf(P.w0[r], x, P.b0[r]);
        v[r] = fmaf(P.tf0[r], tanhf(v[r]), v[r]);
    }
    #pragma unroll
    for (int r = 0; r < 3; r++) {
        u[r] = P.W1[r * 3 + 0] * v[0] + P.W1[r * 3 + 1] * v[1] + P.W1[r * 3 + 2] * v[2] + P.b1[r];
        u[r] = fmaf(P.tf1[r], tanhf(u[r]), u[r]);
    }
    #pragma unroll
    for (int r = 0; r < 3; r++) {
        v[r] = P.W2[r * 3 + 0] * u[0] + P.W2[r * 3 + 1] * u[1] + P.W2[r * 3 + 2] * u[2] + P.b2[r];
        v[r] = fmaf(P.tf2[r], tanhf(v[r]), v[r]);
    }
    float l = P.w3[0] * v[0] + P.w3[1] * v[1] + P.w3[2] * v[2] + P.b3;
    return __fdividef(1.f, 1.f + __expf(-l));
}

__device__ __forceinline__ void affine_quad(float4 zv, float4 p, float4& zh, float4& lk) {
    #pragma unroll
    for (int j = 0; j < 4; j++) {
        float x  = rintf((&zv.x)[j]);                  // round half-to-even == jnp.round
        float t  = fmaf(p.x, x, p.y);
        float E  = __expf(-(t + p.w));                 // e^{-(t+h)}
        float up = __fdividef(1.f, 1.f + E);           // sigmoid(t+h)
        float lo = __fdividef(1.f, fmaf(E, p.z, 1.f)); // sigmoid(t-h): e^{-(t-h)} = E*e^{a}
        (&zh.x)[j] = x;
        (&lk.x)[j] = fmaxf(up - lo, 1e-9f);
    }
}

__global__ void __launch_bounds__(256) fp_main_kernel(const float4* __restrict__ z,
                                                      float* __restrict__ out) {
    int flag = g_flag;
    float4* out_zh = reinterpret_cast<float4*>(out);
    float4* out_lk = reinterpret_cast<float4*>(out + NELEM);

    // ILP=2: each block covers 512 consecutive float4s per sweep.
    for (int base = blockIdx.x * 512 + threadIdx.x; base < N4; base += CHUNK) {
        int i0 = base;
        int i1 = base + 256;          // always < N4 (N4 % 512 == 0)
        int c0 = (i0 >> 10) % NCH;    // 1024 float4 per (b,c) plane
        int c1 = (i1 >> 10) % NCH;

        float4 zv0 = __ldcs(z + i0);
        float4 zv1 = __ldcs(z + i1);
        float4 zh0, lk0, zh1, lk1;

        if (flag == 0) {
            affine_quad(zv0, g_ad[c0], zh0, lk0);
            affine_quad(zv1, g_ad[c1], zh1, lk1);
        } else {
            const ChParams& P0 = g_ch[c0];
            const ChParams& P1 = g_ch[c1];
            #pragma unroll
            for (int j = 0; j < 4; j++) {
                float x0 = rintf((&zv0.x)[j]);
                (&zh0.x)[j] = x0;
                (&lk0.x)[j] = fmaxf(cdf_general(P0, x0 + 0.5f) - cdf_general(P0, x0 - 0.5f), 1e-9f);
                float x1 = rintf((&zv1.x)[j]);
                (&zh1.x)[j] = x1;
                (&lk1.x)[j] = fmaxf(cdf_general(P1, x1 + 0.5f) - cdf_general(P1, x1 - 0.5f), 1e-9f);
            }
        }

        __stcs(out_zh + i0, zh0);
        __stcs(out_zh + i1, zh1);
        __stcs(out_lk + i0, lk0);
        __stcs(out_lk + i1, lk1);
    }
}

extern "C" void kernel_launch(void* const* d_in, const int* in_sizes, int n_in,
                              void* d_out, int out_size) {
    const float* z  = (const float*)d_in[0];
    const float* m0 = (const float*)d_in[1];
    const float* m1 = (const float*)d_in[2];
    const float* m2 = (const float*)d_in[3];
    const float* m3 = (const float*)d_in[4];
    const float* b0 = (const float*)d_in[5];
    const float* b1 = (const float*)d_in[6];
    const float* b2 = (const float*)d_in[7];
    const float* b3 = (const float*)d_in[8];
    const float* f0 = (const float*)d_in[9];
    const float* f1 = (const float*)d_in[10];
    const float* f2 = (const float*)d_in[11];

    setup_kernel<<<1, 256>>>(m0, m1, m2, m3, b0, b1, b2, b3, f0, f1, f2);
    fp_main_kernel<<<GRID_MAIN, 256>>>((const float4*)z, (float*)d_out);
}